// round 12
// baseline (speedup 1.0000x reference)
#include <cuda_runtime.h>
#include <cuda_fp16.h>
#include <math.h>
#include <stdint.h>

#define N_ROWS 4096
#define D_IN   2048
#define D_HID  8192
#define D_OUT  2048
#define RANK   8

// ---------------------------------------------------------------------------
// Static device scratch
// ---------------------------------------------------------------------------
__device__ float g_u[RANK * D_IN];
__device__ float g_T[64];                                       // WY T (8x8, upper)
__device__ __align__(128) __half g_xq[(size_t)N_ROWS * D_IN];
__device__ __align__(128) __half g_wt[(size_t)D_IN * D_HID];    // W_random fp16 [K,N]
__device__ __align__(128) __half g_wo[(size_t)D_HID * D_OUT];   // W_out fp16 [K,N]
__device__ __align__(128) __half g_h[(size_t)N_ROWS * D_HID];   // gelu(h) fp16

// ---------------------------------------------------------------------------
// PTX helpers
// ---------------------------------------------------------------------------
__device__ __forceinline__ uint32_t smem_u32(const void* p) {
    uint32_t a;
    asm("{ .reg .u64 t; cvta.to.shared.u64 t, %1; cvt.u32.u64 %0, t; }" : "=r"(a) : "l"(p));
    return a;
}
__device__ __forceinline__ void cp16(uint32_t s, const void* g) {
    asm volatile("cp.async.cg.shared.global [%0], [%1], 16;" :: "r"(s), "l"(g));
}
#define CP_COMMIT() asm volatile("cp.async.commit_group;" ::: "memory")
#define CP_WAIT(n)  asm volatile("cp.async.wait_group %0;" :: "n"(n) : "memory")

#define LDSM4(r0, r1, r2, r3, addr) \
    asm volatile("ldmatrix.sync.aligned.m8n8.x4.shared.b16 {%0,%1,%2,%3}, [%4];" \
                 : "=r"(r0), "=r"(r1), "=r"(r2), "=r"(r3) : "r"(addr))

#define LDSM4T(r0, r1, r2, r3, addr) \
    asm volatile("ldmatrix.sync.aligned.m8n8.x4.trans.shared.b16 {%0,%1,%2,%3}, [%4];" \
                 : "=r"(r0), "=r"(r1), "=r"(r2), "=r"(r3) : "r"(addr))

#define MMA_F16(c, a, b0, b1) \
    asm volatile("mma.sync.aligned.m16n8k16.row.col.f32.f16.f16.f32 " \
                 "{%0,%1,%2,%3},{%4,%5,%6,%7},{%8,%9},{%0,%1,%2,%3};" \
                 : "+f"((c)[0]), "+f"((c)[1]), "+f"((c)[2]), "+f"((c)[3]) \
                 : "r"((a)[0]), "r"((a)[1]), "r"((a)[2]), "r"((a)[3]), "r"(b0), "r"(b1))

// ---------------------------------------------------------------------------
// 1) Gram-Schmidt (batched-CGS) + WY T matrix. Single block, 256 threads.
// ---------------------------------------------------------------------------
#define GS_SMEM ((RANK + 1) * D_IN * 4)

__global__ void gs_kernel(const float* __restrict__ hra_u,
                          float* __restrict__ u_out, float* __restrict__ Tmat) {
    extern __shared__ float sdyn[];
    float* su  = sdyn;
    float* cur = sdyn + RANK * D_IN;
    __shared__ float swarp[8][8];
    __shared__ float sdots[8];
    __shared__ float sredv[8];
    __shared__ float sG[28];

    const int tid  = threadIdx.x;
    const int lane = tid & 31;
    const int warp = tid >> 5;

    for (int i = 0; i < RANK; i++) {
        #pragma unroll
        for (int e = 0; e < 8; e++) {
            const int d = tid + e * 256;
            cur[d] = hra_u[(size_t)d * RANK + i];
        }
        __syncthreads();

        if (i > 0) {
            float pd[7];
            #pragma unroll
            for (int j = 0; j < 7; j++) pd[j] = 0.f;
            #pragma unroll
            for (int e = 0; e < 8; e++) {
                const int d = tid + e * 256;
                const float c = cur[d];
                #pragma unroll
                for (int j = 0; j < 7; j++)
                    if (j < i) pd[j] += su[j * D_IN + d] * c;
            }
            #pragma unroll
            for (int j = 0; j < 7; j++) {
                #pragma unroll
                for (int o = 16; o > 0; o >>= 1)
                    pd[j] += __shfl_down_sync(0xffffffffu, pd[j], o);
            }
            if (lane == 0) {
                #pragma unroll
                for (int j = 0; j < 7; j++) swarp[warp][j] = pd[j];
            }
            __syncthreads();
            if (tid < 7 && tid < i) {
                float s = 0.f;
                #pragma unroll
                for (int w = 0; w < 8; w++) s += swarp[w][tid];
                sdots[tid] = s;
            }
            __syncthreads();
            #pragma unroll
            for (int e = 0; e < 8; e++) {
                const int d = tid + e * 256;
                float s = 0.f;
                #pragma unroll
                for (int j = 0; j < 7; j++)
                    if (j < i) s += sdots[j] * su[j * D_IN + d];
                cur[d] -= s;
            }
        }

        float nq = 0.f;
        #pragma unroll
        for (int e = 0; e < 8; e++) {
            const int d = tid + e * 256;
            nq += cur[d] * cur[d];
        }
        #pragma unroll
        for (int o = 16; o > 0; o >>= 1) nq += __shfl_down_sync(0xffffffffu, nq, o);
        if (lane == 0) sredv[warp] = nq;
        __syncthreads();
        if (tid == 0) {
            float r = sredv[0];
            #pragma unroll
            for (int w = 1; w < 8; w++) r += sredv[w];
            sredv[0] = 1.0f / (sqrtf(r) + 1e-6f);
        }
        __syncthreads();
        const float inv = sredv[0];
        #pragma unroll
        for (int e = 0; e < 8; e++) {
            const int d = tid + e * 256;
            const float v = cur[d] * inv;
            su[i * D_IN + d] = v;
            u_out[(size_t)i * D_IN + d] = v;
        }
        __syncthreads();
    }

    // Gram pairs + T recurrence
    {
        float pg[28];
        #pragma unroll
        for (int p = 0; p < 28; p++) pg[p] = 0.f;
        #pragma unroll
        for (int e = 0; e < 8; e++) {
            const int d = tid + e * 256;
            float uj[8];
            #pragma unroll
            for (int j = 0; j < 8; j++) uj[j] = su[j * D_IN + d];
            int p = 0;
            #pragma unroll
            for (int k = 1; k < 8; k++)
                #pragma unroll
                for (int j = 0; j < 8; j++)
                    if (j < k) { pg[p] += uj[j] * uj[k]; p++; }
        }
        __shared__ float swg[8][28];
        #pragma unroll
        for (int p = 0; p < 28; p++) {
            #pragma unroll
            for (int o = 16; o > 0; o >>= 1)
                pg[p] += __shfl_down_sync(0xffffffffu, pg[p], o);
        }
        if (lane == 0) {
            #pragma unroll
            for (int p = 0; p < 28; p++) swg[warp][p] = pg[p];
        }
        __syncthreads();
        if (tid < 28) {
            float s = 0.f;
            #pragma unroll
            for (int w = 0; w < 8; w++) s += swg[w][tid];
            sG[tid] = s;
        }
        __syncthreads();
        if (tid == 0) {
            float T[8][8], G[8][8];
            #pragma unroll
            for (int a = 0; a < 8; a++)
                #pragma unroll
                for (int b = 0; b < 8; b++) { T[a][b] = 0.f; G[a][b] = 0.f; }
            int p = 0;
            for (int k = 1; k < 8; k++)
                for (int j = 0; j < k; j++) { G[j][k] = sG[p]; p++; }
            T[0][0] = 2.0f;
            for (int k = 1; k < 8; k++) {
                for (int j = 0; j < k; j++) {
                    float s = 0.f;
                    for (int l = j; l < k; l++) s += T[j][l] * G[l][k];
                    T[j][k] = -2.0f * s;
                }
                T[k][k] = 2.0f;
            }
            for (int a = 0; a < 8; a++)
                for (int b = 0; b < 8; b++) Tmat[a * 8 + b] = T[a][b];
        }
    }
}

// ---------------------------------------------------------------------------
// 2) x @ Q via WY form: v = x - ((xU) T) U^T.
// ---------------------------------------------------------------------------
__global__ void __launch_bounds__(256) hh_kernel(const float* __restrict__ x,
                                                 const float* __restrict__ u,
                                                 const float* __restrict__ Tmat,
                                                 __half* __restrict__ xq) {
    __shared__ float swarp[8][8];
    __shared__ float sdots[8];
    __shared__ float sT[64];
    __shared__ float sq[8];
    const int row  = blockIdx.x;
    const int tid  = threadIdx.x;
    const int lane = tid & 31;
    const int warp = tid >> 5;
    const float* xr = x + (size_t)row * D_IN;

    if (tid < 64) sT[tid] = Tmat[tid];

    float v[8];
    #pragma unroll
    for (int e = 0; e < 8; e++) v[e] = xr[tid + e * 256];

    float pd[8];
    #pragma unroll
    for (int j = 0; j < 8; j++) pd[j] = 0.f;
    #pragma unroll
    for (int e = 0; e < 8; e++) {
        const int d = tid + e * 256;
        const float c = v[e];
        #pragma unroll
        for (int j = 0; j < 8; j++) pd[j] += u[(size_t)j * D_IN + d] * c;
    }
    #pragma unroll
    for (int j = 0; j < 8; j++) {
        #pragma unroll
        for (int o = 16; o > 0; o >>= 1)
            pd[j] += __shfl_down_sync(0xffffffffu, pd[j], o);
    }
    if (lane == 0) {
        #pragma unroll
        for (int j = 0; j < 8; j++) swarp[warp][j] = pd[j];
    }
    __syncthreads();
    if (tid < 8) {
        float s = 0.f;
        #pragma unroll
        for (int w = 0; w < 8; w++) s += swarp[w][tid];
        sdots[tid] = s;
    }
    __syncthreads();
    if (tid < 8) {
        float s = 0.f;
        #pragma unroll
        for (int i = 0; i < 8; i++) s += sdots[i] * sT[i * 8 + tid];
        sq[tid] = s;
    }
    __syncthreads();

    float q[8];
    #pragma unroll
    for (int j = 0; j < 8; j++) q[j] = sq[j];

    #pragma unroll
    for (int e = 0; e < 8; e++) {
        const int d = tid + e * 256;
        float s = 0.f;
        #pragma unroll
        for (int j = 0; j < 8; j++) s += q[j] * u[(size_t)j * D_IN + d];
        xq[(size_t)row * D_IN + d] = __float2half_rn(v[e] - s);
    }
}

// ---------------------------------------------------------------------------
// 3) Coalesced fp32 -> fp16 convert (no transpose needed anymore)
// ---------------------------------------------------------------------------
__global__ void __launch_bounds__(256) convert_half_kernel(
    const float4* __restrict__ in, uint2* __restrict__ outp, int n4) {
    for (int i = blockIdx.x * 256 + threadIdx.x; i < n4; i += gridDim.x * 256) {
        float4 v = in[i];
        __half2 h0 = __floats2half2_rn(v.x, v.y);
        __half2 h1 = __floats2half2_rn(v.z, v.w);
        uint2 o;
        o.x = *reinterpret_cast<uint32_t*>(&h0);
        o.y = *reinterpret_cast<uint32_t*>(&h1);
        outp[i] = o;
    }
}

// ---------------------------------------------------------------------------
// 4) HMMA GEMM: C[M,N] = A[M,K] * B[K,N], fp16, fp32 accum.
//    A row-major [M,K]; B natural [K,N] via ldmatrix.trans (no pre-transpose).
//    Block 128x128, BK=64, 8 warps (2 M x 4 N), warp tile 64x32,
//    3-stage cp.async (CP_WAIT(1)), 2 CTAs/SM, SW128 swizzle,
//    register double-buffered fragments.
// ---------------------------------------------------------------------------
#define BM 128
#define BN 128
#define BK 64
#define STAGES 3
#define A_ROW_B 128                             // 64 fp16 per A row
#define B_ROW_B 256                             // 128 fp16 per B row
#define A_TILE_B (BM * A_ROW_B)                 // 16384
#define B_TILE_B (BK * B_ROW_B)                 // 16384
#define STAGE_BYTES (A_TILE_B + B_TILE_B)       // 32768
#define GEMM_SMEM (STAGES * STAGE_BYTES)        // 98304 -> 2 CTAs/SM

__device__ __forceinline__ void load_stage(uint32_t sb,
                                           const __half* __restrict__ A,
                                           const __half* __restrict__ B,
                                           int m0, int n0, int kc, int K, int Nld,
                                           int tid) {
    // A: 128 rows x 8 chunks (128B rows)
    #pragma unroll
    for (int i = 0; i < 4; i++) {
        const int id = tid + i * 256;
        const int r = id >> 3;
        const int c = id & 7;
        const uint32_t so = (uint32_t)(r * A_ROW_B) + (((uint32_t)(c ^ (r & 7))) << 4);
        cp16(sb + so, A + (size_t)(m0 + r) * K + kc + c * 8);
    }
    // B: 64 rows (k) x 16 chunks (256B rows); swizzle bits[6:4] ^= row&7
    #pragma unroll
    for (int i = 0; i < 4; i++) {
        const int id = tid + i * 256;
        const int r = id >> 4;                  // k-row 0..63
        const int c = id & 15;                  // chunk 0..15
        const uint32_t sc = ((uint32_t)c & 8u) | (((uint32_t)c ^ (uint32_t)(r & 7)) & 7u);
        const uint32_t so = (uint32_t)(r * B_ROW_B) + (sc << 4);
        cp16(sb + A_TILE_B + so, B + (size_t)(kc + r) * Nld + n0 + c * 8);
    }
}

template<int EPI>
__global__ void __launch_bounds__(256, 2) gemm_hmma_f16(
    const __half* __restrict__ A, const __half* __restrict__ B,
    float* __restrict__ Cf, __half* __restrict__ Ch,
    const float* __restrict__ bias, int K, int Nld, int ldc) {
    extern __shared__ char smem[];
    const uint32_t sb = smem_u32(smem);
    const int tid = threadIdx.x;
    const int lane = tid & 31;
    const int wid = tid >> 5;
    const int wm = wid & 1;           // 2 warps along M (64 rows each)
    const int wn = wid >> 1;          // 4 warps along N (32 cols each)
    const int m0 = blockIdx.y * BM;
    const int n0 = blockIdx.x * BN;

    float acc[4][4][4];
    #pragma unroll
    for (int i = 0; i < 4; i++)
        #pragma unroll
        for (int j = 0; j < 4; j++)
            #pragma unroll
            for (int q = 0; q < 4; q++) acc[i][j][q] = 0.f;

    const int NT = K / BK;

    load_stage(sb,               A, B, m0, n0, 0,  K, Nld, tid);
    CP_COMMIT();
    load_stage(sb + STAGE_BYTES, A, B, m0, n0, BK, K, Nld, tid);
    CP_COMMIT();

    // A fragment lane bases (non-trans ldmatrix on [M,K] tile, 128B rows)
    const int rowA  = wm * 64 + (lane & 15);
    const uint32_t partA = ((uint32_t)(lane >> 4)) << 4;
    const uint32_t xorA  = ((uint32_t)(rowA & 7)) << 4;

    // B fragment lane bases (trans ldmatrix on [K,N] tile, 256B rows)
    const int le  = lane & 7;
    const int g1  = (lane >> 3) & 1;            // k +8 group
    const int g2  = lane >> 4;                  // n +8 group
    const uint32_t rowB_off = (uint32_t)((g1 * 8 + le) * B_ROW_B);

    uint32_t af[2][4][4], bf[2][2][4];

#define LOAD_FRAGS(buf, kk, st_) do { \
    const uint32_t cbA = (((uint32_t)(kk) * 32) + partA) ^ xorA; \
    _Pragma("unroll") \
    for (int mt = 0; mt < 4; mt++) { \
        const uint32_t aa = (st_) + (uint32_t)((rowA + mt * 16) * A_ROW_B) + cbA; \
        LDSM4(af[buf][mt][0], af[buf][mt][1], af[buf][mt][2], af[buf][mt][3], aa); \
    } \
    _Pragma("unroll") \
    for (int np = 0; np < 2; np++) { \
        const uint32_t cB = (uint32_t)(wn * 4 + np * 2 + g2); \
        const uint32_t scB = (cB & 8u) | ((cB ^ (uint32_t)le) & 7u); \
        const uint32_t ba = (st_) + A_TILE_B + (uint32_t)((kk) * 16 * B_ROW_B) \
                            + rowB_off + (scB << 4); \
        LDSM4T(bf[buf][np][0], bf[buf][np][1], bf[buf][np][2], bf[buf][np][3], ba); \
    } \
} while (0)

    for (int t = 0; t < NT; t++) {
        CP_WAIT(1);
        __syncthreads();

        if (t + 2 < NT)
            load_stage(sb + ((t + 2) % STAGES) * STAGE_BYTES,
                       A, B, m0, n0, (t + 2) * BK, K, Nld, tid);
        CP_COMMIT();

        const uint32_t st = sb + (t % STAGES) * STAGE_BYTES;
        LOAD_FRAGS(0, 0, st);
        #pragma unroll
        for (int kk = 0; kk < 4; kk++) {
            const int cb = kk & 1;
            if (kk < 3) LOAD_FRAGS(cb ^ 1, kk + 1, st);
            #pragma unroll
            for (int mt = 0; mt < 4; mt++) {
                #pragma unroll
                for (int np = 0; np < 2; np++) {
                    MMA_F16(acc[mt][2 * np],     af[cb][mt], bf[cb][np][0], bf[cb][np][1]);
                    MMA_F16(acc[mt][2 * np + 1], af[cb][mt], bf[cb][np][2], bf[cb][np][3]);
                }
            }
        }
    }
#undef LOAD_FRAGS

    // ---- epilogue
    #pragma unroll
    for (int mt = 0; mt < 4; mt++) {
        const int r0 = m0 + wm * 64 + mt * 16 + (lane >> 2);
        #pragma unroll
        for (int nt = 0; nt < 4; nt++) {
            const int col = n0 + wn * 32 + nt * 8 + (lane & 3) * 2;
            const float* a4 = acc[mt][nt];
            if (EPI == 0) {
                #pragma unroll
                for (int h = 0; h < 2; h++) {
                    const int rr = r0 + h * 8;
                    float v0 = a4[2 * h + 0], v1 = a4[2 * h + 1];
                    v0 = 0.5f * v0 * (1.0f + erff(v0 * 0.70710678118654752f));
                    v1 = 0.5f * v1 * (1.0f + erff(v1 * 0.70710678118654752f));
                    uint32_t ph = (uint32_t)__half_as_ushort(__float2half_rn(v0)) |
                                  ((uint32_t)__half_as_ushort(__float2half_rn(v1)) << 16);
                    *(uint32_t*)(Ch + (size_t)rr * ldc + col) = ph;
                }
            } else {
                const float b0 = __ldg(bias + col);
                const float b1 = __ldg(bias + col + 1);
                #pragma unroll
                for (int h = 0; h < 2; h++) {
                    const int rr = r0 + h * 8;
                    float2 v;
                    v.x = a4[2 * h + 0] + b0;
                    v.y = a4[2 * h + 1] + b1;
                    *(float2*)(Cf + (size_t)rr * ldc + col) = v;
                }
            }
        }
    }
}

// ---------------------------------------------------------------------------
// Launcher. Forked capture stream overlaps weight converts with gs+hh.
// ---------------------------------------------------------------------------
extern "C" void kernel_launch(void* const* d_in, const int* in_sizes, int n_in,
                              void* d_out, int out_size) {
    const float* x        = (const float*)d_in[0];
    const float* hra_u    = (const float*)d_in[1];
    const float* W_random = (const float*)d_in[2];
    const float* W_out    = (const float*)d_in[3];
    const float* bias     = (const float*)d_in[4];
    float*       out      = (float*)d_out;

    float *u_p, *T_p; __half *xq, *wt, *wo, *hp;
    cudaGetSymbolAddress((void**)&u_p, g_u);
    cudaGetSymbolAddress((void**)&T_p, g_T);
    cudaGetSymbolAddress((void**)&xq,  g_xq);
    cudaGetSymbolAddress((void**)&wt,  g_wt);
    cudaGetSymbolAddress((void**)&wo,  g_wo);
    cudaGetSymbolAddress((void**)&hp,  g_h);

    static cudaStream_t s2 = nullptr;
    static cudaEvent_t ev_fork = nullptr, ev_join = nullptr;
    if (!s2) {
        cudaStreamCreateWithFlags(&s2, cudaStreamNonBlocking);
        cudaEventCreateWithFlags(&ev_fork, cudaEventDisableTiming);
        cudaEventCreateWithFlags(&ev_join, cudaEventDisableTiming);
        cudaFuncSetAttribute(gs_kernel, cudaFuncAttributeMaxDynamicSharedMemorySize, GS_SMEM);
        cudaFuncSetAttribute(gemm_hmma_f16<0>, cudaFuncAttributeMaxDynamicSharedMemorySize, GEMM_SMEM);
        cudaFuncSetAttribute(gemm_hmma_f16<1>, cudaFuncAttributeMaxDynamicSharedMemorySize, GEMM_SMEM);
    }

    // fork: weight converts on s2, parallel with gs+hh on main stream
    cudaEventRecord(ev_fork, 0);
    cudaStreamWaitEvent(s2, ev_fork, 0);
    convert_half_kernel<<<2048, 256, 0, s2>>>(
        (const float4*)W_random, (uint2*)wt, (int)((size_t)D_IN * D_HID / 4));
    convert_half_kernel<<<2048, 256, 0, s2>>>(
        (const float4*)W_out, (uint2*)wo, (int)((size_t)D_HID * D_OUT / 4));
    cudaEventRecord(ev_join, s2);

    gs_kernel<<<1, 256, GS_SMEM>>>(hra_u, u_p, T_p);
    hh_kernel<<<N_ROWS, 256>>>(x, u_p, T_p, xq);

    cudaStreamWaitEvent(0, ev_join, 0);   // join before GEMMs need weights

    // GEMM1: h = gelu(xq @ W_t)   M=4096, N=8192, K=2048 (B = wt [2048,8192])
    gemm_hmma_f16<0><<<dim3(D_HID / BN, N_ROWS / BM), 256, GEMM_SMEM>>>(
        xq, wt, nullptr, hp, nullptr, D_IN, D_HID, D_HID);

    // GEMM2: out = h @ W_out + bias   M=4096, N=2048, K=8192 (B = wo [8192,2048])
    gemm_hmma_f16<1><<<dim3(D_OUT / BN, N_ROWS / BM), 256, GEMM_SMEM>>>(
        hp, wo, out, nullptr, bias, D_HID, D_OUT, D_OUT);
}

// round 13
// speedup vs baseline: 1.0403x; 1.0403x over previous
#include <cuda_runtime.h>
#include <cuda_fp16.h>
#include <math.h>
#include <stdint.h>

#define N_ROWS 4096
#define D_IN   2048
#define D_HID  8192
#define D_OUT  2048
#define RANK   8

// ---------------------------------------------------------------------------
// Static device scratch
// ---------------------------------------------------------------------------
__device__ float g_u[RANK * D_IN];
__device__ float g_T[64];
__device__ __align__(128) __half g_xq[(size_t)N_ROWS * D_IN];
__device__ __align__(128) __half g_wt[(size_t)D_HID * D_IN];    // W_random^T [N,K]
__device__ __align__(128) __half g_wo[(size_t)D_OUT * D_HID];   // W_out^T    [N,K]
__device__ __align__(128) __half g_h[(size_t)N_ROWS * D_HID];

// ---------------------------------------------------------------------------
// PTX helpers
// ---------------------------------------------------------------------------
__device__ __forceinline__ uint32_t smem_u32(const void* p) {
    uint32_t a;
    asm("{ .reg .u64 t; cvta.to.shared.u64 t, %1; cvt.u32.u64 %0, t; }" : "=r"(a) : "l"(p));
    return a;
}
__device__ __forceinline__ void cp16(uint32_t s, const void* g) {
    asm volatile("cp.async.cg.shared.global [%0], [%1], 16;" :: "r"(s), "l"(g));
}
#define CP_COMMIT() asm volatile("cp.async.commit_group;" ::: "memory")

#define LDSM4(r0, r1, r2, r3, addr) \
    asm volatile("ldmatrix.sync.aligned.m8n8.x4.shared.b16 {%0,%1,%2,%3}, [%4];" \
                 : "=r"(r0), "=r"(r1), "=r"(r2), "=r"(r3) : "r"(addr))

#define MMA_F16(c, a, b0, b1) \
    asm volatile("mma.sync.aligned.m16n8k16.row.col.f32.f16.f16.f32 " \
                 "{%0,%1,%2,%3},{%4,%5,%6,%7},{%8,%9},{%0,%1,%2,%3};" \
                 : "+f"((c)[0]), "+f"((c)[1]), "+f"((c)[2]), "+f"((c)[3]) \
                 : "r"((a)[0]), "r"((a)[1]), "r"((a)[2]), "r"((a)[3]), "r"(b0), "r"(b1))

// ---------------------------------------------------------------------------
// 1) Gram-Schmidt (batched-CGS) + WY T matrix. Single block, 256 threads.
// ---------------------------------------------------------------------------
#define GS_SMEM ((RANK + 1) * D_IN * 4)

__global__ void gs_kernel(const float* __restrict__ hra_u,
                          float* __restrict__ u_out, float* __restrict__ Tmat) {
    extern __shared__ float sdyn[];
    float* su  = sdyn;
    float* cur = sdyn + RANK * D_IN;
    __shared__ float swarp[8][8];
    __shared__ float sdots[8];
    __shared__ float sredv[8];
    __shared__ float sG[28];

    const int tid  = threadIdx.x;
    const int lane = tid & 31;
    const int warp = tid >> 5;

    for (int i = 0; i < RANK; i++) {
        #pragma unroll
        for (int e = 0; e < 8; e++) {
            const int d = tid + e * 256;
            cur[d] = hra_u[(size_t)d * RANK + i];
        }
        __syncthreads();

        if (i > 0) {
            float pd[7];
            #pragma unroll
            for (int j = 0; j < 7; j++) pd[j] = 0.f;
            #pragma unroll
            for (int e = 0; e < 8; e++) {
                const int d = tid + e * 256;
                const float c = cur[d];
                #pragma unroll
                for (int j = 0; j < 7; j++)
                    if (j < i) pd[j] += su[j * D_IN + d] * c;
            }
            #pragma unroll
            for (int j = 0; j < 7; j++) {
                #pragma unroll
                for (int o = 16; o > 0; o >>= 1)
                    pd[j] += __shfl_down_sync(0xffffffffu, pd[j], o);
            }
            if (lane == 0) {
                #pragma unroll
                for (int j = 0; j < 7; j++) swarp[warp][j] = pd[j];
            }
            __syncthreads();
            if (tid < 7 && tid < i) {
                float s = 0.f;
                #pragma unroll
                for (int w = 0; w < 8; w++) s += swarp[w][tid];
                sdots[tid] = s;
            }
            __syncthreads();
            #pragma unroll
            for (int e = 0; e < 8; e++) {
                const int d = tid + e * 256;
                float s = 0.f;
                #pragma unroll
                for (int j = 0; j < 7; j++)
                    if (j < i) s += sdots[j] * su[j * D_IN + d];
                cur[d] -= s;
            }
        }

        float nq = 0.f;
        #pragma unroll
        for (int e = 0; e < 8; e++) {
            const int d = tid + e * 256;
            nq += cur[d] * cur[d];
        }
        #pragma unroll
        for (int o = 16; o > 0; o >>= 1) nq += __shfl_down_sync(0xffffffffu, nq, o);
        if (lane == 0) sredv[warp] = nq;
        __syncthreads();
        if (tid == 0) {
            float r = sredv[0];
            #pragma unroll
            for (int w = 1; w < 8; w++) r += sredv[w];
            sredv[0] = 1.0f / (sqrtf(r) + 1e-6f);
        }
        __syncthreads();
        const float inv = sredv[0];
        #pragma unroll
        for (int e = 0; e < 8; e++) {
            const int d = tid + e * 256;
            const float v = cur[d] * inv;
            su[i * D_IN + d] = v;
            u_out[(size_t)i * D_IN + d] = v;
        }
        __syncthreads();
    }

    {
        float pg[28];
        #pragma unroll
        for (int p = 0; p < 28; p++) pg[p] = 0.f;
        #pragma unroll
        for (int e = 0; e < 8; e++) {
            const int d = tid + e * 256;
            float uj[8];
            #pragma unroll
            for (int j = 0; j < 8; j++) uj[j] = su[j * D_IN + d];
            int p = 0;
            #pragma unroll
            for (int k = 1; k < 8; k++)
                #pragma unroll
                for (int j = 0; j < 8; j++)
                    if (j < k) { pg[p] += uj[j] * uj[k]; p++; }
        }
        __shared__ float swg[8][28];
        #pragma unroll
        for (int p = 0; p < 28; p++) {
            #pragma unroll
            for (int o = 16; o > 0; o >>= 1)
                pg[p] += __shfl_down_sync(0xffffffffu, pg[p], o);
        }
        if (lane == 0) {
            #pragma unroll
            for (int p = 0; p < 28; p++) swg[warp][p] = pg[p];
        }
        __syncthreads();
        if (tid < 28) {
            float s = 0.f;
            #pragma unroll
            for (int w = 0; w < 8; w++) s += swg[w][tid];
            sG[tid] = s;
        }
        __syncthreads();
        if (tid == 0) {
            float T[8][8], G[8][8];
            #pragma unroll
            for (int a = 0; a < 8; a++)
                #pragma unroll
                for (int b = 0; b < 8; b++) { T[a][b] = 0.f; G[a][b] = 0.f; }
            int p = 0;
            for (int k = 1; k < 8; k++)
                for (int j = 0; j < k; j++) { G[j][k] = sG[p]; p++; }
            T[0][0] = 2.0f;
            for (int k = 1; k < 8; k++) {
                for (int j = 0; j < k; j++) {
                    float s = 0.f;
                    for (int l = j; l < k; l++) s += T[j][l] * G[l][k];
                    T[j][k] = -2.0f * s;
                }
                T[k][k] = 2.0f;
            }
            for (int a = 0; a < 8; a++)
                for (int b = 0; b < 8; b++) Tmat[a * 8 + b] = T[a][b];
        }
    }
}

// ---------------------------------------------------------------------------
// 2) x @ Q via WY form: v = x - ((xU) T) U^T.
// ---------------------------------------------------------------------------
__global__ void __launch_bounds__(256) hh_kernel(const float* __restrict__ x,
                                                 const float* __restrict__ u,
                                                 const float* __restrict__ Tmat,
                                                 __half* __restrict__ xq) {
    __shared__ float swarp[8][8];
    __shared__ float sdots[8];
    __shared__ float sT[64];
    __shared__ float sq[8];
    const int row  = blockIdx.x;
    const int tid  = threadIdx.x;
    const int lane = tid & 31;
    const int warp = tid >> 5;
    const float* xr = x + (size_t)row * D_IN;

    if (tid < 64) sT[tid] = Tmat[tid];

    float v[8];
    #pragma unroll
    for (int e = 0; e < 8; e++) v[e] = xr[tid + e * 256];

    float pd[8];
    #pragma unroll
    for (int j = 0; j < 8; j++) pd[j] = 0.f;
    #pragma unroll
    for (int e = 0; e < 8; e++) {
        const int d = tid + e * 256;
        const float c = v[e];
        #pragma unroll
        for (int j = 0; j < 8; j++) pd[j] += u[(size_t)j * D_IN + d] * c;
    }
    #pragma unroll
    for (int j = 0; j < 8; j++) {
        #pragma unroll
        for (int o = 16; o > 0; o >>= 1)
            pd[j] += __shfl_down_sync(0xffffffffu, pd[j], o);
    }
    if (lane == 0) {
        #pragma unroll
        for (int j = 0; j < 8; j++) swarp[warp][j] = pd[j];
    }
    __syncthreads();
    if (tid < 8) {
        float s = 0.f;
        #pragma unroll
        for (int w = 0; w < 8; w++) s += swarp[w][tid];
        sdots[tid] = s;
    }
    __syncthreads();
    if (tid < 8) {
        float s = 0.f;
        #pragma unroll
        for (int i = 0; i < 8; i++) s += sdots[i] * sT[i * 8 + tid];
        sq[tid] = s;
    }
    __syncthreads();

    float q[8];
    #pragma unroll
    for (int j = 0; j < 8; j++) q[j] = sq[j];

    #pragma unroll
    for (int e = 0; e < 8; e++) {
        const int d = tid + e * 256;
        float s = 0.f;
        #pragma unroll
        for (int j = 0; j < 8; j++) s += q[j] * u[(size_t)j * D_IN + d];
        xq[(size_t)row * D_IN + d] = __float2half_rn(v[e] - s);
    }
}

// ---------------------------------------------------------------------------
// 3) Transpose to fp16: in[R,C] fp32 -> out[C,R] fp16
// ---------------------------------------------------------------------------
__global__ void __launch_bounds__(256) transpose_half_kernel(
    const float* __restrict__ in, __half* __restrict__ outp, int R, int C) {
    __shared__ float tile[32][33];
    const int c0 = blockIdx.x * 32, r0 = blockIdx.y * 32;
    const int tx = threadIdx.x, ty = threadIdx.y;
    #pragma unroll
    for (int j = 0; j < 32; j += 8)
        tile[ty + j][tx] = in[(size_t)(r0 + ty + j) * C + c0 + tx];
    __syncthreads();
    #pragma unroll
    for (int j = 0; j < 32; j += 8) {
        float v = tile[tx][ty + j];
        outp[(size_t)(c0 + ty + j) * R + r0 + tx] = __float2half_rn(v);
    }
}

// ---------------------------------------------------------------------------
// 4) Templated HMMA GEMM: C[M,N] = A[M,K] * B[N,K]^T, fp16, fp32 accum.
//    8 warps as 2(M) x 4(N); warp tile (TBM/2) x 32.
//    TST-stage cp.async, 2 CTAs/SM, SW128 swizzle, frag double-buffer.
// ---------------------------------------------------------------------------
template<int TBM, int TBK>
__device__ __forceinline__ void load_stage_t(uint32_t sb,
                                             const __half* __restrict__ A,
                                             const __half* __restrict__ B,
                                             int m0, int n0, int kc, int K, int tid) {
    constexpr int CH   = TBK / 8;           // 16B chunks per row
    constexpr int ROWB = TBK * 2;
    constexpr int AIT  = TBM * CH / 256;
    constexpr int BIT  = 128 * CH / 256;    // BN = 128
    constexpr int ATILE = TBM * ROWB;
    #pragma unroll
    for (int i = 0; i < AIT; i++) {
        const int id = tid + i * 256;
        const int r = id / CH;
        const int c = id % CH;
        const uint32_t so = (uint32_t)(r * ROWB) + (((uint32_t)(c ^ (r & 7))) << 4);
        cp16(sb + so, A + (size_t)(m0 + r) * K + kc + c * 8);
    }
    #pragma unroll
    for (int i = 0; i < BIT; i++) {
        const int id = tid + i * 256;
        const int r = id / CH;
        const int c = id % CH;
        const uint32_t so = (uint32_t)(r * ROWB) + (((uint32_t)(c ^ (r & 7))) << 4);
        cp16(sb + ATILE + so, B + (size_t)(n0 + r) * K + kc + c * 8);
    }
}

template<int EPI, int TBM, int TBK, int TST>
__global__ void __launch_bounds__(256, 2) gemm_hmma_f16(
    const __half* __restrict__ A, const __half* __restrict__ B,
    float* __restrict__ Cf, __half* __restrict__ Ch,
    const float* __restrict__ bias, int K, int ldc) {
    constexpr int ROWB  = TBK * 2;
    constexpr int ATILE = TBM * ROWB;
    constexpr int BTILE = 128 * ROWB;
    constexpr int STB   = ATILE + BTILE;
    constexpr int MT    = TBM / 32;          // mma tiles along M per warp
    constexpr int KK    = TBK / 16;

    extern __shared__ char smem[];
    const uint32_t sb = smem_u32(smem);
    const int tid = threadIdx.x;
    const int lane = tid & 31;
    const int wid = tid >> 5;
    const int wm = wid & 1;
    const int wn = wid >> 1;
    const int m0 = blockIdx.y * TBM;
    const int n0 = blockIdx.x * 128;

    float acc[MT][4][4];
    #pragma unroll
    for (int i = 0; i < MT; i++)
        #pragma unroll
        for (int j = 0; j < 4; j++)
            #pragma unroll
            for (int q = 0; q < 4; q++) acc[i][j][q] = 0.f;

    const int NT = K / TBK;

    #pragma unroll
    for (int s = 0; s < TST - 1; s++) {
        load_stage_t<TBM, TBK>(sb + s * STB, A, B, m0, n0, s * TBK, K, tid);
        CP_COMMIT();
    }

    const int rowA  = wm * (TBM / 2) + (lane & 15);
    const uint32_t partA = ((uint32_t)(lane >> 4)) << 4;
    const uint32_t xorA  = ((uint32_t)(rowA & 7)) << 4;
    const int rowB  = wn * 32 + (lane & 7) + ((lane >> 4) << 3);
    const uint32_t partB = ((uint32_t)((lane >> 3) & 1)) << 4;
    const uint32_t xorB  = ((uint32_t)(rowB & 7)) << 4;

    uint32_t af[2][MT][4], bf[2][2][4];

#define LOAD_FRAGS(buf, kk, st_) do { \
    const uint32_t cbA = (((uint32_t)(kk) * 32) + partA) ^ xorA; \
    const uint32_t cbB = (((uint32_t)(kk) * 32) + partB) ^ xorB; \
    _Pragma("unroll") \
    for (int mt = 0; mt < MT; mt++) { \
        const uint32_t aa = (st_) + (uint32_t)((rowA + mt * 16) * ROWB) + cbA; \
        LDSM4(af[buf][mt][0], af[buf][mt][1], af[buf][mt][2], af[buf][mt][3], aa); \
    } \
    _Pragma("unroll") \
    for (int np = 0; np < 2; np++) { \
        const uint32_t ba = (st_) + ATILE + (uint32_t)((rowB + np * 16) * ROWB) + cbB; \
        LDSM4(bf[buf][np][0], bf[buf][np][1], bf[buf][np][2], bf[buf][np][3], ba); \
    } \
} while (0)

    for (int t = 0; t < NT; t++) {
        asm volatile("cp.async.wait_group %0;" :: "n"(TST - 2) : "memory");
        __syncthreads();

        if (t + TST - 1 < NT)
            load_stage_t<TBM, TBK>(sb + ((t + TST - 1) % TST) * STB,
                                   A, B, m0, n0, (t + TST - 1) * TBK, K, tid);
        CP_COMMIT();

        const uint32_t st = sb + (t % TST) * STB;
        LOAD_FRAGS(0, 0, st);
        #pragma unroll
        for (int kk = 0; kk < KK; kk++) {
            const int cb = kk & 1;
            if (kk < KK - 1) LOAD_FRAGS(cb ^ 1, kk + 1, st);
            #pragma unroll
            for (int mt = 0; mt < MT; mt++) {
                #pragma unroll
                for (int np = 0; np < 2; np++) {
                    MMA_F16(acc[mt][2 * np],     af[cb][mt], bf[cb][np][0], bf[cb][np][1]);
                    MMA_F16(acc[mt][2 * np + 1], af[cb][mt], bf[cb][np][2], bf[cb][np][3]);
                }
            }
        }
        if (TST == 2) __syncthreads();   // 2-stage: protect slot reuse next iter
    }
#undef LOAD_FRAGS

    // ---- epilogue
    #pragma unroll
    for (int mt = 0; mt < MT; mt++) {
        const int r0 = m0 + wm * (TBM / 2) + mt * 16 + (lane >> 2);
        #pragma unroll
        for (int nt = 0; nt < 4; nt++) {
            const int col = n0 + wn * 32 + nt * 8 + (lane & 3) * 2;
            const float* a4 = acc[mt][nt];
            if (EPI == 0) {
                #pragma unroll
                for (int h = 0; h < 2; h++) {
                    const int rr = r0 + h * 8;
                    float v0 = a4[2 * h + 0], v1 = a4[2 * h + 1];
                    v0 = 0.5f * v0 * (1.0f + erff(v0 * 0.70710678118654752f));
                    v1 = 0.5f * v1 * (1.0f + erff(v1 * 0.70710678118654752f));
                    uint32_t ph = (uint32_t)__half_as_ushort(__float2half_rn(v0)) |
                                  ((uint32_t)__half_as_ushort(__float2half_rn(v1)) << 16);
                    *(uint32_t*)(Ch + (size_t)rr * ldc + col) = ph;
                }
            } else {
                const float b0 = __ldg(bias + col);
                const float b1 = __ldg(bias + col + 1);
                #pragma unroll
                for (int h = 0; h < 2; h++) {
                    const int rr = r0 + h * 8;
                    float2 v;
                    v.x = a4[2 * h + 0] + b0;
                    v.y = a4[2 * h + 1] + b1;
                    *(float2*)(Cf + (size_t)rr * ldc + col) = v;
                }
            }
        }
    }
}

// GEMM1: 128x128x64, 3-stage (best measured GEMM1). smem = 3*32768 = 98304.
// GEMM2: 64x128x128, 2-stage (1024 CTAs, small tail). smem = 2*49152 = 98304.
#define GEMM_SMEM 98304

// ---------------------------------------------------------------------------
// Launcher. Fork: transposes on s2 overlap gs+hh on main stream.
// ---------------------------------------------------------------------------
extern "C" void kernel_launch(void* const* d_in, const int* in_sizes, int n_in,
                              void* d_out, int out_size) {
    const float* x        = (const float*)d_in[0];
    const float* hra_u    = (const float*)d_in[1];
    const float* W_random = (const float*)d_in[2];
    const float* W_out    = (const float*)d_in[3];
    const float* bias     = (const float*)d_in[4];
    float*       out      = (float*)d_out;

    float *u_p, *T_p; __half *xq, *wt, *wo, *hp;
    cudaGetSymbolAddress((void**)&u_p, g_u);
    cudaGetSymbolAddress((void**)&T_p, g_T);
    cudaGetSymbolAddress((void**)&xq,  g_xq);
    cudaGetSymbolAddress((void**)&wt,  g_wt);
    cudaGetSymbolAddress((void**)&wo,  g_wo);
    cudaGetSymbolAddress((void**)&hp,  g_h);

    static cudaStream_t s2 = nullptr;
    static cudaEvent_t ev_fork = nullptr, ev_join = nullptr;
    if (!s2) {
        cudaStreamCreateWithFlags(&s2, cudaStreamNonBlocking);
        cudaEventCreateWithFlags(&ev_fork, cudaEventDisableTiming);
        cudaEventCreateWithFlags(&ev_join, cudaEventDisableTiming);
        cudaFuncSetAttribute(gs_kernel, cudaFuncAttributeMaxDynamicSharedMemorySize, GS_SMEM);
        cudaFuncSetAttribute(gemm_hmma_f16<0, 128, 64, 3>,
                             cudaFuncAttributeMaxDynamicSharedMemorySize, GEMM_SMEM);
        cudaFuncSetAttribute(gemm_hmma_f16<1, 64, 128, 2>,
                             cudaFuncAttributeMaxDynamicSharedMemorySize, GEMM_SMEM);
    }

    // fork: weight transposes on s2, parallel with gs+hh on main stream
    cudaEventRecord(ev_fork, 0);
    cudaStreamWaitEvent(s2, ev_fork, 0);
    transpose_half_kernel<<<dim3(D_HID / 32, D_IN / 32), dim3(32, 8), 0, s2>>>(
        W_random, wt, D_IN, D_HID);
    transpose_half_kernel<<<dim3(D_OUT / 32, D_HID / 32), dim3(32, 8), 0, s2>>>(
        W_out, wo, D_HID, D_OUT);
    cudaEventRecord(ev_join, s2);

    gs_kernel<<<1, 256, GS_SMEM>>>(hra_u, u_p, T_p);
    hh_kernel<<<N_ROWS, 256>>>(x, u_p, T_p, xq);

    cudaStreamWaitEvent(0, ev_join, 0);

    // GEMM1: h = gelu(xq @ Wt^T)   M=4096, N=8192, K=2048
    gemm_hmma_f16<0, 128, 64, 3><<<dim3(D_HID / 128, N_ROWS / 128), 256, GEMM_SMEM>>>(
        xq, wt, nullptr, hp, nullptr, D_IN, D_HID);

    // GEMM2: out = h @ Wo^T + bias   M=4096, N=2048, K=8192
    gemm_hmma_f16<1, 64, 128, 2><<<dim3(D_OUT / 128, N_ROWS / 64), 256, GEMM_SMEM>>>(
        hp, wo, out, nullptr, bias, D_HID, D_OUT);
}